// round 1
// baseline (speedup 1.0000x reference)
#include <cuda_runtime.h>

#define NN 1000000
#define NE 8000000
#define NEG_SLOPE 0.01f

// Scratch (device globals — no runtime allocation allowed).
__device__ float g_h[(size_t)NN * 64];      // projected features, both channels: [N][64]
__device__ float g_ex[(size_t)2 * NE];      // exp(logit), planar per channel: [2][E]
__device__ float g_denom[2 * NN];           // softmax denominators, planar: [2][N]

__global__ void __launch_bounds__(256) k_zero_denom() {
    int i = blockIdx.x * 256 + threadIdx.x;
    if (i < 2 * NN) g_denom[i] = 0.f;
}

// h[n][c*32+d] = leaky( sum_k ego[n][k] * W[c][k][d] + b[c][d] )
__global__ void __launch_bounds__(256) k_project(const float* __restrict__ ego,
                                                 const float* __restrict__ W,
                                                 const float* __restrict__ b) {
    __shared__ float sW[4096];   // W[c][k][d] = sW[c*2048 + k*32 + d]
    __shared__ float sb[64];     // b[c][d]   = sb[c*32 + d]
    for (int i = threadIdx.x; i < 4096; i += 256) sW[i] = W[i];
    if (threadIdx.x < 64) sb[threadIdx.x] = b[threadIdx.x];
    __syncthreads();

    int n = blockIdx.x * 256 + threadIdx.x;
    if (n >= NN) return;

    float x[64];
    const float4* xi = (const float4*)(ego + (size_t)n * 64);
#pragma unroll
    for (int j = 0; j < 16; j++) {
        float4 v = xi[j];
        x[4*j+0] = v.x; x[4*j+1] = v.y; x[4*j+2] = v.z; x[4*j+3] = v.w;
    }

    float4* ho = (float4*)(g_h + (size_t)n * 64);
    for (int g = 0; g < 8; g++) {          // 8 output dims per group, 8 groups
        int c  = g >> 2;
        int d0 = (g & 3) * 8;
        const float* wp = &sW[c * 2048 + d0];
        float a0 = sb[g*8+0], a1 = sb[g*8+1], a2 = sb[g*8+2], a3 = sb[g*8+3];
        float a4 = sb[g*8+4], a5 = sb[g*8+5], a6 = sb[g*8+6], a7 = sb[g*8+7];
#pragma unroll
        for (int k = 0; k < 64; k++) {
            float4 wa = *(const float4*)(wp + k * 32);
            float4 wb = *(const float4*)(wp + k * 32 + 4);
            float xv = x[k];
            a0 += xv * wa.x; a1 += xv * wa.y; a2 += xv * wa.z; a3 += xv * wa.w;
            a4 += xv * wb.x; a5 += xv * wb.y; a6 += xv * wb.z; a7 += xv * wb.w;
        }
        a0 = a0 > 0.f ? a0 : NEG_SLOPE * a0;
        a1 = a1 > 0.f ? a1 : NEG_SLOPE * a1;
        a2 = a2 > 0.f ? a2 : NEG_SLOPE * a2;
        a3 = a3 > 0.f ? a3 : NEG_SLOPE * a3;
        a4 = a4 > 0.f ? a4 : NEG_SLOPE * a4;
        a5 = a5 > 0.f ? a5 : NEG_SLOPE * a5;
        a6 = a6 > 0.f ? a6 : NEG_SLOPE * a6;
        a7 = a7 > 0.f ? a7 : NEG_SLOPE * a7;
        ho[g*2 + 0] = make_float4(a0, a1, a2, a3);
        ho[g*2 + 1] = make_float4(a4, a5, a6, a7);
    }
}

// Per edge: logits -> exp -> store ex, accumulate denominator per destination row.
// No segment_max needed: logits are bounded (<~60) so exp() cannot overflow fp32,
// and since sum(exp) >= exp(max), the EPS term stays negligible exactly as in ref.
__global__ void __launch_bounds__(256) k_edge(const int* __restrict__ row,
                                              const int* __restrict__ col) {
    int e = blockIdx.x * 256 + threadIdx.x;
    if (e >= NE) return;
    int r = row[e], c = col[e];
    const float4* hr = (const float4*)(g_h + (size_t)r * 64);
    const float4* hc = (const float4*)(g_h + (size_t)c * 64);
    float d0 = 0.f, d1 = 0.f;
#pragma unroll
    for (int j = 0; j < 8; j++) {
        float4 a = hr[j]; float4 b = hc[j];
        d0 += a.x*b.x + a.y*b.y + a.z*b.z + a.w*b.w;
    }
#pragma unroll
    for (int j = 8; j < 16; j++) {
        float4 a = hr[j]; float4 b = hc[j];
        d1 += a.x*b.x + a.y*b.y + a.z*b.z + a.w*b.w;
    }
    d0 = d0 > 0.f ? d0 : NEG_SLOPE * d0;
    d1 = d1 > 0.f ? d1 : NEG_SLOPE * d1;
    float e0 = __expf(d0);
    float e1 = __expf(d1);
    g_ex[e]      = e0;
    g_ex[NE + e] = e1;
    atomicAdd(&g_denom[r], e0);
    atomicAdd(&g_denom[NN + r], e1);
}

__device__ __forceinline__ void red_v4(float* p, float a, float b, float c, float d) {
    asm volatile("red.global.add.v4.f32 [%0], {%1,%2,%3,%4};"
                 :: "l"(p), "f"(a), "f"(b), "f"(c), "f"(d) : "memory");
}

// Per edge: alpha = ex / (denom + eps); scatter alpha * h[col] into out[row].
__global__ void __launch_bounds__(256) k_aggr(const int* __restrict__ row,
                                              const int* __restrict__ col,
                                              float* __restrict__ out) {
    int e = blockIdx.x * 256 + threadIdx.x;
    if (e >= NE) return;
    int r = row[e], c = col[e];
    float a0 = g_ex[e]      / (g_denom[r]      + 1e-10f);
    float a1 = g_ex[NE + e] / (g_denom[NN + r] + 1e-10f);
    const float4* hc = (const float4*)(g_h + (size_t)c * 64);
    float* ob = out + (size_t)r * 64;
#pragma unroll
    for (int j = 0; j < 8; j++) {
        float4 v = hc[j];
        red_v4(ob + j * 4, a0 * v.x, a0 * v.y, a0 * v.z, a0 * v.w);
    }
#pragma unroll
    for (int j = 8; j < 16; j++) {
        float4 v = hc[j];
        red_v4(ob + j * 4, a1 * v.x, a1 * v.y, a1 * v.z, a1 * v.w);
    }
}

extern "C" void kernel_launch(void* const* d_in, const int* in_sizes, int n_in,
                              void* d_out, int out_size) {
    const float* ego = (const float*)d_in[0];
    const float* W   = (const float*)d_in[1];
    const float* b   = (const float*)d_in[2];
    const int*   row = (const int*)d_in[3];
    const int*   col = (const int*)d_in[4];
    float* out = (float*)d_out;

    cudaMemsetAsync(d_out, 0, (size_t)out_size * sizeof(float), 0);
    k_zero_denom<<<(2 * NN + 255) / 256, 256>>>();
    k_project<<<(NN + 255) / 256, 256>>>(ego, W, b);
    k_edge<<<(NE + 255) / 256, 256>>>(row, col);
    k_aggr<<<(NE + 255) / 256, 256>>>(row, col, out);
}

// round 2
// speedup vs baseline: 3.6866x; 3.6866x over previous
#include <cuda_runtime.h>

#define NN 1000000
#define NE 8000000
#define NEG_SLOPE 0.01f
#define CHUNK 4096
#define NCHUNK ((NN + CHUNK - 1) / CHUNK)   // 245

// Scratch (device globals — no runtime allocation allowed).
__device__ float g_h[(size_t)NN * 64];   // projected features, both channels: [N][64]
__device__ int   g_cnt[NN];              // per-row edge count
__device__ int   g_start[NN];            // CSR row start
__device__ int   g_cursor[NN];           // scatter cursors (init = start)
__device__ int   g_ecol[NE];             // CSR column indices
__device__ int   g_csum[NCHUNK];         // chunk sums for scan
__device__ int   g_coff[NCHUNK];         // exclusive chunk offsets

__global__ void __launch_bounds__(256) k_zero_cnt() {
    int i = blockIdx.x * 256 + threadIdx.x;
    if (i < NN) g_cnt[i] = 0;
}

__global__ void __launch_bounds__(256) k_count(const int* __restrict__ row) {
    int e = blockIdx.x * 256 + threadIdx.x;
    if (e < NE) atomicAdd(&g_cnt[row[e]], 1);
}

// scan stage 1: per-chunk totals
__global__ void __launch_bounds__(256) k_scan1() {
    __shared__ int sred[256];
    int b = blockIdx.x, t = threadIdx.x;
    int base = b * CHUNK + t * 16;
    int s = 0;
#pragma unroll
    for (int i = 0; i < 16; i++) {
        int idx = base + i;
        if (idx < NN) s += g_cnt[idx];
    }
    sred[t] = s;
    __syncthreads();
    for (int o = 128; o > 0; o >>= 1) {
        if (t < o) sred[t] += sred[t + o];
        __syncthreads();
    }
    if (t == 0) g_csum[b] = sred[0];
}

// scan stage 2: exclusive scan of chunk sums (single block)
__global__ void __launch_bounds__(256) k_scan2() {
    __shared__ int s[NCHUNK];
    int t = threadIdx.x;
    if (t < NCHUNK) s[t] = g_csum[t];
    __syncthreads();
    if (t == 0) {
        int acc = 0;
        for (int i = 0; i < NCHUNK; i++) { int v = s[i]; s[i] = acc; acc += v; }
    }
    __syncthreads();
    if (t < NCHUNK) g_coff[t] = s[t];
}

// scan stage 3: per-element exclusive scan, write start + cursor
__global__ void __launch_bounds__(256) k_scan3() {
    __shared__ int sthr[256];
    int b = blockIdx.x, t = threadIdx.x;
    int base = b * CHUNK + t * 16;
    int local[16];
    int s = 0;
#pragma unroll
    for (int i = 0; i < 16; i++) {
        int idx = base + i;
        local[i] = (idx < NN) ? g_cnt[idx] : 0;
        s += local[i];
    }
    sthr[t] = s;
    __syncthreads();
    // Hillis-Steele inclusive scan over 256 thread sums
    for (int o = 1; o < 256; o <<= 1) {
        int v = (t >= o) ? sthr[t - o] : 0;
        __syncthreads();
        sthr[t] += v;
        __syncthreads();
    }
    int pre = g_coff[b] + ((t > 0) ? sthr[t - 1] : 0);
#pragma unroll
    for (int i = 0; i < 16; i++) {
        int idx = base + i;
        if (idx < NN) { g_start[idx] = pre; g_cursor[idx] = pre; pre += local[i]; }
    }
}

__global__ void __launch_bounds__(256) k_scatter(const int* __restrict__ row,
                                                 const int* __restrict__ col) {
    int e = blockIdx.x * 256 + threadIdx.x;
    if (e < NE) {
        int r = row[e];
        int pos = atomicAdd(&g_cursor[r], 1);
        g_ecol[pos] = col[e];
    }
}

// h[n][c*32+d] = leaky( sum_k ego[n][k] * W[c][k][d] + b[c][d] )
__global__ void __launch_bounds__(256) k_project(const float* __restrict__ ego,
                                                 const float* __restrict__ W,
                                                 const float* __restrict__ b) {
    __shared__ float sW[4096];   // W[c][k][d] = sW[c*2048 + k*32 + d]
    __shared__ float sb[64];
    for (int i = threadIdx.x; i < 4096; i += 256) sW[i] = W[i];
    if (threadIdx.x < 64) sb[threadIdx.x] = b[threadIdx.x];
    __syncthreads();

    int n = blockIdx.x * 256 + threadIdx.x;
    if (n >= NN) return;

    float x[64];
    const float4* xi = (const float4*)(ego + (size_t)n * 64);
#pragma unroll
    for (int j = 0; j < 16; j++) {
        float4 v = xi[j];
        x[4*j+0] = v.x; x[4*j+1] = v.y; x[4*j+2] = v.z; x[4*j+3] = v.w;
    }

    float4* ho = (float4*)(g_h + (size_t)n * 64);
    for (int g = 0; g < 8; g++) {
        int c  = g >> 2;
        int d0 = (g & 3) * 8;
        const float* wp = &sW[c * 2048 + d0];
        float a0 = sb[g*8+0], a1 = sb[g*8+1], a2 = sb[g*8+2], a3 = sb[g*8+3];
        float a4 = sb[g*8+4], a5 = sb[g*8+5], a6 = sb[g*8+6], a7 = sb[g*8+7];
#pragma unroll
        for (int k = 0; k < 64; k++) {
            float4 wa = *(const float4*)(wp + k * 32);
            float4 wb = *(const float4*)(wp + k * 32 + 4);
            float xv = x[k];
            a0 += xv * wa.x; a1 += xv * wa.y; a2 += xv * wa.z; a3 += xv * wa.w;
            a4 += xv * wb.x; a5 += xv * wb.y; a6 += xv * wb.z; a7 += xv * wb.w;
        }
        a0 = a0 > 0.f ? a0 : NEG_SLOPE * a0;
        a1 = a1 > 0.f ? a1 : NEG_SLOPE * a1;
        a2 = a2 > 0.f ? a2 : NEG_SLOPE * a2;
        a3 = a3 > 0.f ? a3 : NEG_SLOPE * a3;
        a4 = a4 > 0.f ? a4 : NEG_SLOPE * a4;
        a5 = a5 > 0.f ? a5 : NEG_SLOPE * a5;
        a6 = a6 > 0.f ? a6 : NEG_SLOPE * a6;
        a7 = a7 > 0.f ? a7 : NEG_SLOPE * a7;
        ho[g*2 + 0] = make_float4(a0, a1, a2, a3);
        ho[g*2 + 1] = make_float4(a4, a5, a6, a7);
    }
}

// Fused edge-softmax + aggregation: one warp per destination row.
// out[r] = (sum_e ex_e * h[col_e]) / (sum_e ex_e + eps), per channel.
// No segment_max needed: logits bounded (<~60) so exp cannot overflow fp32;
// since sum(exp) >= exp(max) the EPS term is negligible exactly as in the ref.
// Lane l owns dims {2l, 2l+1}; channel = l>>4 (dims 0-31 / 32-63).
__global__ void __launch_bounds__(256) k_row(float* __restrict__ out) {
    int warp = (blockIdx.x * 256 + threadIdx.x) >> 5;
    int lane = threadIdx.x & 31;
    if (warp >= NN) return;
    int r = warp;
    int s = g_start[r];
    int n = g_cnt[r];

    float2 hr = *(const float2*)(g_h + (size_t)r * 64 + lane * 2);
    float accx = 0.f, accy = 0.f, dsum = 0.f;

    int c_next = (n > 0) ? g_ecol[s] : 0;
    for (int i = 0; i < n; i++) {
        int c = c_next;
        if (i + 1 < n) c_next = g_ecol[s + i + 1];
        float2 v = *(const float2*)(g_h + (size_t)c * 64 + lane * 2);
        float p = hr.x * v.x + hr.y * v.y;
        // reduce within each 16-lane group (channel)
        p += __shfl_xor_sync(0xffffffffu, p, 8);
        p += __shfl_xor_sync(0xffffffffu, p, 4);
        p += __shfl_xor_sync(0xffffffffu, p, 2);
        p += __shfl_xor_sync(0xffffffffu, p, 1);
        p = p > 0.f ? p : NEG_SLOPE * p;
        float ex = __expf(p);
        dsum += ex;
        accx += ex * v.x;
        accy += ex * v.y;
    }
    float inv = 1.f / (dsum + 1e-10f);
    *(float2*)(out + (size_t)r * 64 + lane * 2) = make_float2(accx * inv, accy * inv);
}

extern "C" void kernel_launch(void* const* d_in, const int* in_sizes, int n_in,
                              void* d_out, int out_size) {
    const float* ego = (const float*)d_in[0];
    const float* W   = (const float*)d_in[1];
    const float* b   = (const float*)d_in[2];
    const int*   row = (const int*)d_in[3];
    const int*   col = (const int*)d_in[4];
    float* out = (float*)d_out;

    k_zero_cnt<<<(NN + 255) / 256, 256>>>();
    k_count<<<(NE + 255) / 256, 256>>>(row);
    k_scan1<<<NCHUNK, 256>>>();
    k_scan2<<<1, 256>>>();
    k_scan3<<<NCHUNK, 256>>>();
    k_scatter<<<(NE + 255) / 256, 256>>>(row, col);
    k_project<<<(NN + 255) / 256, 256>>>(ego, W, b);
    k_row<<<(NN * 32 + 255) / 256, 256>>>(out);
}